// round 16
// baseline (speedup 1.0000x reference)
#include <cuda_runtime.h>
#include <cuda_fp16.h>

#define H 256
#define D 8
#define BN_EPS 1e-5f
#define NBLK 296
#define CHUNK_TILES 7
#define CHUNK (CHUNK_TILES * 256)          /* 1792 edges per worker block */
#define MAXE_FUSED ((NBLK - 1) * CHUNK)    /* 528640 */

typedef unsigned long long u64;
typedef unsigned int u32;

// ---------------- mma helpers ----------------
__device__ __forceinline__ void mma_16x8x8(
    float& d0, float& d1, float& d2, float& d3,
    u32 a0, u32 a1, u32 b0,
    float c0, float c1, float c2, float c3) {
    asm volatile("mma.sync.aligned.m16n8k8.row.col.f32.f16.f16.f32 "
        "{%0,%1,%2,%3}, {%4,%5}, {%6}, {%7,%8,%9,%10};"
        : "=f"(d0), "=f"(d1), "=f"(d2), "=f"(d3)
        : "r"(a0), "r"(a1), "r"(b0), "f"(c0), "f"(c1), "f"(c2), "f"(c3));
}
__device__ __forceinline__ u32 cvt_f16x2(float hi, float lo) {
    u32 d; asm("cvt.rn.f16x2.f32 %0, %1, %2;" : "=r"(d) : "f"(hi), "f"(lo)); return d;
}

// ---------------- device scratch ----------------
__device__ float g_P [H * D];
__device__ float g_T2[H * D];
__device__ float g_M [H * D];
__device__ float g_c [D];
__device__ float g_sum  [H];
__device__ float g_sumsq[H];
__device__ float g_Ms[H * D];            // fallback path only
__device__ float g_c8[D];                // fallback path only
__device__ volatile int g_bar;

// ---------------- init: zero stats + barrier ----------------
__global__ void k_init() {
    int t = threadIdx.x;
    g_sum[t] = 0.f; g_sumsq[t] = 0.f;
    if (t == 0) g_bar = 0;
}

// =========================================================================
// FUSED persistent kernel
// =========================================================================
__global__ void __launch_bounds__(256, 2) k_fused(
    const float* __restrict__ ea, const float* __restrict__ nf,
    const int* __restrict__ ei,
    const float* __restrict__ W1, const float* __restrict__ b1,
    const float* __restrict__ gamma, const float* __restrict__ beta,
    const float* __restrict__ Wo, const float* __restrict__ Wp,
    const float* __restrict__ Wv, const float* __restrict__ W2,
    const float* __restrict__ b2, const float* __restrict__ bv,
    const float* __restrict__ bo, const float* __restrict__ bp,
    float* __restrict__ out, int E, float invE) {

    __shared__ __align__(16) uint4 ncs4[CHUNK];   // 28672 B fp16 nc cache
    __shared__ u32    w1f[32][32];                // 4096
    __shared__ u32    msf[32][32];                // 4096
    __shared__ float2 b1pS[32][4];                // 1024
    __shared__ float  svs[H];                     // 1024  (0.5*s)
    __shared__ float  tvs[H];                     // 1024
    __shared__ float  c8s[D];

    const int t = threadIdx.x, lane = t & 31, warp = t >> 5;
    const int q = lane & 3, g = lane >> 2;

    // ---- stage W1 B-fragments + bias pairs (all blocks) ----
    for (int idx = t; idx < 1024; idx += 256) {
        int ch = idx >> 5, ln = idx & 31;
        int k0 = (ln & 3) * 2, n = ln >> 2;
        __half2 hw = __floats2half2_rn(W1[k0 * H + ch * 8 + n],
                                       W1[(k0 + 1) * H + ch * 8 + n]);
        w1f[ch][ln] = *(u32*)&hw;
    }
    for (int idx = t; idx < 128; idx += 256) {
        int ch = idx >> 2, qq = idx & 3;
        b1pS[ch][qq] = make_float2(b1[ch * 8 + qq * 2], b1[ch * 8 + qq * 2 + 1]);
    }

    // ---- per-warp phase-1 fragments: warp owns hidden chunks 4w..4w+3 ----
    u32   wfrag[4];
    float bias0[4], bias1[4];
#pragma unroll
    for (int i = 0; i < 4; i++) {
        int ch = warp * 4 + i;
        int n = ch * 8 + g, k0 = q * 2;
        wfrag[i] = cvt_f16x2(W1[(k0 + 1) * H + n], W1[k0 * H + n]);
        bias0[i] = b1[ch * 8 + q * 2];
        bias1[i] = b1[ch * 8 + q * 2 + 1];
    }

    const int wb = (int)blockIdx.x - 1;           // block 0 = fold worker
    const long base = (long)wb * CHUNK;
    int cnt = 0;
    if (wb >= 0) {
        long rem = (long)E - base;
        cnt = rem <= 0 ? 0 : (rem >= CHUNK ? CHUNK : (int)rem);
    }

    // ---- gather + cvt entire chunk into smem cache ----
    for (int i = t; i < CHUNK; i += 256) {
        uint4 pk = make_uint4(0, 0, 0, 0);
        if (i < cnt) {
            int e = (int)base + i;
            int s0 = ei[e], s1 = ei[E + e];
            const float4* a = (const float4*)(nf + (size_t)s0 * D);
            const float4* b = (const float4*)(nf + (size_t)s1 * D);
            float4 x0 = a[0], x1 = a[1], y0 = b[0], y1 = b[1];
            pk.x = cvt_f16x2(0.5f * (x0.y + y0.y), 0.5f * (x0.x + y0.x));
            pk.y = cvt_f16x2(0.5f * (x0.w + y0.w), 0.5f * (x0.z + y0.z));
            pk.z = cvt_f16x2(0.5f * (x1.y + y1.y), 0.5f * (x1.x + y1.x));
            pk.w = cvt_f16x2(0.5f * (x1.w + y1.w), 0.5f * (x1.z + y1.z));
        }
        ncs4[i] = pk;
    }

    // ---- block 0: weight folds P -> T2 -> M, c (hidden under others' phase 1) ----
    if (blockIdx.x == 0) {
        for (int idx = t; idx < H * D; idx += 256) {
            int i = idx >> 3, d = idx & 7;
            float acc = 0.f;
#pragma unroll 8
            for (int k = 0; k < H; k++) acc = fmaf(Wo[i * H + k], Wp[k * D + d], acc);
            g_P[idx] = acc;
        }
        __syncthreads();
        for (int idx = t; idx < H * D; idx += 256) {
            int i = idx >> 3, d = idx & 7;
            float acc = 0.f;
#pragma unroll 8
            for (int k = 0; k < H; k++) acc = fmaf(Wv[i * H + k], g_P[k * D + d], acc);
            g_T2[idx] = acc;
        }
        __syncthreads();
        for (int idx = t; idx < H * D; idx += 256) {
            int i = idx >> 3, d = idx & 7;
            float acc = 0.f;
#pragma unroll 8
            for (int k = 0; k < H; k++) acc = fmaf(W2[i * H + k], g_T2[k * D + d], acc);
            g_M[idx] = acc;
        }
        if (t < D) {
            float c = bp[t];
            for (int k = 0; k < H; k++) {
                c = fmaf(b2[k], g_T2[k * D + t], c);
                c = fmaf(bv[k], g_P [k * D + t], c);
                c = fmaf(bo[k], Wp  [k * D + t], c);
            }
            g_c[t] = c;
        }
    }
    __syncthreads();

    // ---- phase 1: HMMA stats over smem cache ----
    if (cnt > 0) {
        float sum0[4], sum1[4], ssq0[4], ssq1[4];
#pragma unroll
        for (int i = 0; i < 4; i++) { sum0[i] = sum1[i] = ssq0[i] = ssq1[i] = 0.f; }
        const u32* ncsw = (const u32*)ncs4;

        if (cnt == CHUNK) {
#pragma unroll 2
            for (int sub = 0; sub < CHUNK / 16; sub++) {
                int r0 = sub * 16 + g;
                u32 a0 = ncsw[r0 * 4 + q];
                u32 a1 = ncsw[(r0 + 8) * 4 + q];
#pragma unroll
                for (int i = 0; i < 4; i++) {
                    float q0, q1, q2, q3;
                    mma_16x8x8(q0, q1, q2, q3, a0, a1, wfrag[i],
                               bias0[i], bias1[i], bias0[i], bias1[i]);
                    float h0 = fmaxf(q0, 0.f), h1 = fmaxf(q1, 0.f);
                    float h2 = fmaxf(q2, 0.f), h3 = fmaxf(q3, 0.f);
                    sum0[i] += h0 + h2;  sum1[i] += h1 + h3;
                    ssq0[i] = fmaf(h0, h0, fmaf(h2, h2, ssq0[i]));
                    ssq1[i] = fmaf(h1, h1, fmaf(h3, h3, ssq1[i]));
                }
            }
        } else {
            const int nsub = (cnt + 15) >> 4;
            for (int sub = 0; sub < nsub; sub++) {
                int r0 = sub * 16 + g;
                const float m0 = (r0 < cnt)     ? 1.f : 0.f;
                const float m1 = (r0 + 8 < cnt) ? 1.f : 0.f;
                u32 a0 = ncsw[r0 * 4 + q];
                u32 a1 = ncsw[(r0 + 8) * 4 + q];
#pragma unroll
                for (int i = 0; i < 4; i++) {
                    float q0, q1, q2, q3;
                    mma_16x8x8(q0, q1, q2, q3, a0, a1, wfrag[i],
                               bias0[i], bias1[i], bias0[i], bias1[i]);
                    float h0 = fmaxf(q0, 0.f) * m0, h1 = fmaxf(q1, 0.f) * m0;
                    float h2 = fmaxf(q2, 0.f) * m1, h3 = fmaxf(q3, 0.f) * m1;
                    sum0[i] += h0 + h2;  sum1[i] += h1 + h3;
                    ssq0[i] = fmaf(h0, h0, fmaf(h2, h2, ssq0[i]));
                    ssq1[i] = fmaf(h1, h1, fmaf(h3, h3, ssq1[i]));
                }
            }
        }
#pragma unroll
        for (int i = 0; i < 4; i++) {
#pragma unroll
            for (int off = 4; off < 32; off <<= 1) {
                sum0[i] += __shfl_xor_sync(0xFFFFFFFFu, sum0[i], off);
                sum1[i] += __shfl_xor_sync(0xFFFFFFFFu, sum1[i], off);
                ssq0[i] += __shfl_xor_sync(0xFFFFFFFFu, ssq0[i], off);
                ssq1[i] += __shfl_xor_sync(0xFFFFFFFFu, ssq1[i], off);
            }
            if (g == 0) {
                int c0 = (warp * 4 + i) * 8 + q * 2;
                atomicAdd(&g_sum  [c0],     sum0[i]);
                atomicAdd(&g_sum  [c0 + 1], sum1[i]);
                atomicAdd(&g_sumsq[c0],     ssq0[i]);
                atomicAdd(&g_sumsq[c0 + 1], ssq1[i]);
            }
        }
    }

    // ---- software grid barrier ----
    __syncthreads();
    if (t == 0) {
        __threadfence();
        atomicAdd((int*)&g_bar, 1);
        while (g_bar < (int)gridDim.x) __nanosleep(64);
        __threadfence();
    }
    __syncthreads();

    // ---- inline finalize (every block, redundant) ----
    {
        int j = t;                     // blockDim == H
        float mu  = g_sum[j]   * invE;
        float eh2 = g_sumsq[j] * invE;
        float var = fmaf(-mu, mu, eh2);
        float s   = gamma[j] * rsqrtf(var + BN_EPS);
        svs[j] = 0.5f * s;
        tvs[j] = fmaf(-mu, s, beta[j]);
    }
    __syncthreads();
    for (int idx = t; idx < 1024; idx += 256) {
        int ch = idx >> 5, ln = idx & 31;
        int k0 = (ln & 3) * 2, n = ln >> 2;
        int j0 = ch * 8 + k0, j1 = j0 + 1;
        __half2 hm = __floats2half2_rn(svs[j0] * g_M[j0 * D + n],
                                       svs[j1] * g_M[j1 * D + n]);
        msf[ch][ln] = *(u32*)&hm;
    }
    if (t < D) {
        float acc = g_c[t];
        for (int k = 0; k < H; k++) acc = fmaf(tvs[k], g_M[k * D + t], acc);
        c8s[t] = 0.5f * acc;
    }
    __syncthreads();

    // ---- phase 2: GEMM1 -> relu -> GEMM2 from smem cache; no gather ----
    if (cnt > 0) {
        const u32* ncsw = (const u32*)ncs4;
        const int nsub = (cnt + 15) >> 4;
        const int dcol = q * 2;
        for (int sub = warp; sub < nsub; sub += 8) {
            int r0 = sub * 16 + g;
            u32 a0 = ncsw[r0 * 4 + q];
            u32 a1 = ncsw[(r0 + 8) * 4 + q];

            float ae0 = 0.f, ae1 = 0.f, ae2 = 0.f, ae3 = 0.f;
            float ao0 = 0.f, ao1 = 0.f, ao2 = 0.f, ao3 = 0.f;
#pragma unroll 4
            for (int ch = 0; ch < 32; ch++) {
                u32 wbv = w1f[ch][lane];
                float2 bb = b1pS[ch][q];
                float q0, q1, q2, q3;
                mma_16x8x8(q0, q1, q2, q3, a0, a1, wbv, bb.x, bb.y, bb.x, bb.y);
                q0 = fmaxf(q0, 0.f); q1 = fmaxf(q1, 0.f);
                q2 = fmaxf(q2, 0.f); q3 = fmaxf(q3, 0.f);
                u32 rh0 = cvt_f16x2(q1, q0);
                u32 rh1 = cvt_f16x2(q3, q2);
                u32 mb = msf[ch][lane];
                if (ch & 1) mma_16x8x8(ao0, ao1, ao2, ao3, rh0, rh1, mb, ao0, ao1, ao2, ao3);
                else        mma_16x8x8(ae0, ae1, ae2, ae3, rh0, rh1, mb, ae0, ae1, ae2, ae3);
            }

            const float cx = c8s[dcol], cy = c8s[dcol + 1];
            int ge0 = (int)base + r0;
            int ge1 = ge0 + 8;
            if (ge0 < E) {
                float2 eav = *(const float2*)(ea + (size_t)ge0 * D + dcol);
                float2 o = make_float2(eav.x + ae0 + ao0 + cx,
                                       eav.y + ae1 + ao1 + cy);
                *(float2*)(out + (size_t)ge0 * D + dcol) = o;
            }
            if (ge1 < E) {
                float2 eav = *(const float2*)(ea + (size_t)ge1 * D + dcol);
                float2 o = make_float2(eav.x + ae2 + ao2 + cx,
                                       eav.y + ae3 + ao3 + cy);
                *(float2*)(out + (size_t)ge1 * D + dcol) = o;
            }
        }
    }
}

// =========================================================================
// Fallback path (R14, proven) — used only if E > MAXE_FUSED
// =========================================================================
__global__ void k_fold1(const float* __restrict__ Wo, const float* __restrict__ Wp) {
    int t = blockIdx.x * blockDim.x + threadIdx.x;
    int i = t >> 3, d = t & 7;
    float acc = 0.f;
#pragma unroll 8
    for (int k = 0; k < H; k++) acc = fmaf(Wo[i * H + k], Wp[k * D + d], acc);
    g_P[i * D + d] = acc;
    if (t < H) { g_sum[t] = 0.f; g_sumsq[t] = 0.f; }
}
__global__ void k_fold2(const float* __restrict__ Wv) {
    int t = blockIdx.x * blockDim.x + threadIdx.x;
    int i = t >> 3, d = t & 7;
    float acc = 0.f;
#pragma unroll 8
    for (int k = 0; k < H; k++) acc = fmaf(Wv[i * H + k], g_P[k * D + d], acc);
    g_T2[i * D + d] = acc;
}
__global__ void k_fold3(const float* __restrict__ W2, const float* __restrict__ b2,
                        const float* __restrict__ bv, const float* __restrict__ bo,
                        const float* __restrict__ bp, const float* __restrict__ Wp) {
    int t = blockIdx.x * blockDim.x + threadIdx.x;
    int i = t >> 3, d = t & 7;
    float acc = 0.f;
#pragma unroll 8
    for (int k = 0; k < H; k++) acc = fmaf(W2[i * H + k], g_T2[k * D + d], acc);
    g_M[i * D + d] = acc;
    if (t < D) {
        float c = bp[t];
        for (int k = 0; k < H; k++) {
            c = fmaf(b2[k], g_T2[k * D + t], c);
            c = fmaf(bv[k], g_P [k * D + t], c);
            c = fmaf(bo[k], Wp  [k * D + t], c);
        }
        g_c[t] = c;
    }
}
__global__ void __launch_bounds__(256) k_pass1t(
    const float* __restrict__ nf, const int* __restrict__ ei,
    const float* __restrict__ W1, const float* __restrict__ b1, int E) {
    __shared__ __align__(16) uint4 ncs4[256];
    const int t = threadIdx.x, lane = t & 31, warp = t >> 5;
    const int q = lane & 3, g = lane >> 2;
    u32 wfrag[4]; float bias0[4], bias1[4];
#pragma unroll
    for (int i = 0; i < 4; i++) {
        int ch = warp * 4 + i;
        int n = ch * 8 + g, k0 = q * 2;
        wfrag[i] = cvt_f16x2(W1[(k0 + 1) * H + n], W1[k0 * H + n]);
        bias0[i] = b1[ch * 8 + q * 2];
        bias1[i] = b1[ch * 8 + q * 2 + 1];
    }
    float sum0[4], sum1[4], ssq0[4], ssq1[4];
#pragma unroll
    for (int i = 0; i < 4; i++) { sum0[i] = sum1[i] = ssq0[i] = ssq1[i] = 0.f; }
    const u32* ncsw = (const u32*)ncs4;
    const int numTiles = (E + 255) >> 8;
    for (int tile = blockIdx.x; tile < numTiles; tile += gridDim.x) {
        const int base = tile << 8;
        const int cnt  = min(256, E - base);
        __syncthreads();
        {
            uint4 pk = make_uint4(0, 0, 0, 0);
            if (t < cnt) {
                int e = base + t;
                int s0 = ei[e], s1 = ei[E + e];
                const float4* a = (const float4*)(nf + (size_t)s0 * D);
                const float4* b = (const float4*)(nf + (size_t)s1 * D);
                float4 x0 = a[0], x1 = a[1], y0 = b[0], y1 = b[1];
                pk.x = cvt_f16x2(0.5f * (x0.y + y0.y), 0.5f * (x0.x + y0.x));
                pk.y = cvt_f16x2(0.5f * (x0.w + y0.w), 0.5f * (x0.z + y0.z));
                pk.z = cvt_f16x2(0.5f * (x1.y + y1.y), 0.5f * (x1.x + y1.x));
                pk.w = cvt_f16x2(0.5f * (x1.w + y1.w), 0.5f * (x1.z + y1.z));
            }
            ncs4[t] = pk;
        }
        __syncthreads();
        const int nsub = (cnt + 15) >> 4;
        for (int sub = 0; sub < nsub; sub++) {
            int r0 = sub * 16 + g;
            const float m0 = (r0 < cnt)     ? 1.f : 0.f;
            const float m1 = (r0 + 8 < cnt) ? 1.f : 0.f;
            u32 a0 = ncsw[r0 * 4 + q];
            u32 a1 = ncsw[(r0 + 8) * 4 + q];
#pragma unroll
            for (int i = 0; i < 4; i++) {
                float q0, q1, q2, q3;
                mma_16x8x8(q0, q1, q2, q3, a0, a1, wfrag[i],
                           bias0[i], bias1[i], bias0[i], bias1[i]);
                float h0 = fmaxf(q0, 0.f) * m0, h1 = fmaxf(q1, 0.f) * m0;
                float h2 = fmaxf(q2, 0.f) * m1, h3 = fmaxf(q3, 0.f) * m1;
                sum0[i] += h0 + h2;  sum1[i] += h1 + h3;
                ssq0[i] = fmaf(h0, h0, fmaf(h2, h2, ssq0[i]));
                ssq1[i] = fmaf(h1, h1, fmaf(h3, h3, ssq1[i]));
            }
        }
    }
#pragma unroll
    for (int i = 0; i < 4; i++) {
#pragma unroll
        for (int off = 4; off < 32; off <<= 1) {
            sum0[i] += __shfl_xor_sync(0xFFFFFFFFu, sum0[i], off);
            sum1[i] += __shfl_xor_sync(0xFFFFFFFFu, sum1[i], off);
            ssq0[i] += __shfl_xor_sync(0xFFFFFFFFu, ssq0[i], off);
            ssq1[i] += __shfl_xor_sync(0xFFFFFFFFu, ssq1[i], off);
        }
        if (g == 0) {
            int c0 = (warp * 4 + i) * 8 + q * 2;
            atomicAdd(&g_sum  [c0],     sum0[i]);
            atomicAdd(&g_sum  [c0 + 1], sum1[i]);
            atomicAdd(&g_sumsq[c0],     ssq0[i]);
            atomicAdd(&g_sumsq[c0 + 1], ssq1[i]);
        }
    }
}
__global__ void k_finalize(const float* __restrict__ gamma,
                           const float* __restrict__ beta, float invE) {
    __shared__ float tvs[H];
    const int j = threadIdx.x;
    float mu  = g_sum[j]   * invE;
    float eh2 = g_sumsq[j] * invE;
    float var = fmaf(-mu, mu, eh2);
    float s   = gamma[j] * rsqrtf(var + BN_EPS);
    float tv  = fmaf(-mu, s, beta[j]);
#pragma unroll
    for (int d = 0; d < D; d++) g_Ms[j * D + d] = 0.5f * s * g_M[j * D + d];
    tvs[j] = tv;
    __syncthreads();
    if (j < D) {
        float acc = g_c[j];
        for (int k = 0; k < H; k++) acc = fmaf(tvs[k], g_M[k * D + j], acc);
        g_c8[j] = 0.5f * acc;
    }
}
__global__ void __launch_bounds__(256) k_pass2t(
    const float* __restrict__ ea, const float* __restrict__ nf,
    const int* __restrict__ ei,
    const float* __restrict__ W1, const float* __restrict__ b1,
    float* __restrict__ out, int E) {
    __shared__ u32    w1f[32][32];
    __shared__ u32    msf[32][32];
    __shared__ float2 b1p[32][4];
    __shared__ float2 c8p[4];
    const int t = threadIdx.x;
    for (int idx = t; idx < 1024; idx += 256) {
        int ch = idx >> 5, ln = idx & 31;
        int k0 = (ln & 3) * 2, n = ln >> 2;
        __half2 hw = __floats2half2_rn(W1[k0 * H + ch * 8 + n],
                                       W1[(k0 + 1) * H + ch * 8 + n]);
        w1f[ch][ln] = *(u32*)&hw;
        __half2 hm = __floats2half2_rn(g_Ms[(ch * 8 + k0) * D + n],
                                       g_Ms[(ch * 8 + k0 + 1) * D + n]);
        msf[ch][ln] = *(u32*)&hm;
    }
    for (int idx = t; idx < 128; idx += 256) {
        int ch = idx >> 2, qq = idx & 3;
        b1p[ch][qq] = make_float2(b1[ch * 8 + qq * 2], b1[ch * 8 + qq * 2 + 1]);
    }
    if (t < 4) c8p[t] = make_float2(g_c8[t * 2], g_c8[t * 2 + 1]);
    __syncthreads();
    const int lane = t & 31;
    const int gwarp = blockIdx.x * 8 + (t >> 5);
    const int nwarps = gridDim.x * 8;
    const int ntiles = (E + 15) >> 4;
    const int dcol = (lane & 3) * 2;
    for (int g = gwarp; g < ntiles; g += nwarps) {
        const int base = g << 4;
        const int r0 = base + (lane >> 2);
        const int r1 = r0 + 8;
        const int e0 = min(r0, E - 1);
        const int e1 = min(r1, E - 1);
        u32 a0, a1;
        {
            int s0 = ei[e0], s1 = ei[E + e0];
            float2 u = *(const float2*)(nf + (size_t)s0 * D + dcol);
            float2 v = *(const float2*)(nf + (size_t)s1 * D + dcol);
            a0 = cvt_f16x2(0.5f * (u.y + v.y), 0.5f * (u.x + v.x));
            int s2 = ei[e1], s3 = ei[E + e1];
            float2 p = *(const float2*)(nf + (size_t)s2 * D + dcol);
            float2 qv = *(const float2*)(nf + (size_t)s3 * D + dcol);
            a1 = cvt_f16x2(0.5f * (p.y + qv.y), 0.5f * (p.x + qv.x));
        }
        float ae0 = 0.f, ae1 = 0.f, ae2 = 0.f, ae3 = 0.f;
        float ao0 = 0.f, ao1 = 0.f, ao2 = 0.f, ao3 = 0.f;
#pragma unroll 4
        for (int ch = 0; ch < 32; ch++) {
            u32 wb = w1f[ch][lane];
            float2 bb = b1p[ch][lane & 3];
            float q0, q1, q2, q3;
            mma_16x8x8(q0, q1, q2, q3, a0, a1, wb, bb.x, bb.y, bb.x, bb.y);
            q0 = fmaxf(q0, 0.f); q1 = fmaxf(q1, 0.f);
            q2 = fmaxf(q2, 0.f); q3 = fmaxf(q3, 0.f);
            u32 rh0 = cvt_f16x2(q1, q0);
            u32 rh1 = cvt_f16x2(q3, q2);
            u32 mb = msf[ch][lane];
            if (ch & 1) mma_16x8x8(ao0, ao1, ao2, ao3, rh0, rh1, mb, ao0, ao1, ao2, ao3);
            else        mma_16x8x8(ae0, ae1, ae2, ae3, rh0, rh1, mb, ae0, ae1, ae2, ae3);
        }
        const float2 c8v = c8p[lane & 3];
        if (r0 < E) {
            float2 eav = *(const float2*)(ea + (size_t)r0 * D + dcol);
            float2 o = make_float2(eav.x + ae0 + ao0 + c8v.x,
                                   eav.y + ae1 + ao1 + c8v.y);
            *(float2*)(out + (size_t)r0 * D + dcol) = o;
        }
        if (r1 < E) {
            float2 eav = *(const float2*)(ea + (size_t)r1 * D + dcol);
            float2 o = make_float2(eav.x + ae2 + ao2 + c8v.x,
                                   eav.y + ae3 + ao3 + c8v.y);
            *(float2*)(out + (size_t)r1 * D + dcol) = o;
        }
    }
}

// ---------------- launcher ----------------
extern "C" void kernel_launch(void* const* d_in, const int* in_sizes, int n_in,
                              void* d_out, int out_size) {
    const float* edge_attr     = (const float*)d_in[0];
    const float* node_features = (const float*)d_in[1];
    const int*   edge_index    = (const int*)  d_in[2];
    // d_in[3..8]: edge-encoder params — unused by the reference output
    const float* n_W1    = (const float*)d_in[9];
    const float* n_b1    = (const float*)d_in[10];
    const float* n_gamma = (const float*)d_in[11];
    const float* n_beta  = (const float*)d_in[12];
    const float* n_W2    = (const float*)d_in[13];
    const float* n_b2    = (const float*)d_in[14];
    const float* Wv      = (const float*)d_in[15];
    const float* bv      = (const float*)d_in[16];
    const float* Wo      = (const float*)d_in[17];
    const float* bo      = (const float*)d_in[18];
    const float* Wp      = (const float*)d_in[19];
    const float* bp      = (const float*)d_in[20];

    const int E = in_sizes[0] / D;
    float* out = (float*)d_out;

    if (E <= MAXE_FUSED) {
        k_init<<<1, 256>>>();
        k_fused<<<NBLK, 256>>>(edge_attr, node_features, edge_index,
                               n_W1, n_b1, n_gamma, n_beta,
                               Wo, Wp, Wv, n_W2, n_b2, bv, bo, bp,
                               out, E, 1.0f / (float)E);
    } else {
        k_fold1<<<16, 128>>>(Wo, Wp);
        k_fold2<<<16, 128>>>(Wv);
        k_fold3<<<16, 128>>>(n_W2, n_b2, bv, bo, bp, Wp);
        k_pass1t<<<1184, 256>>>(node_features, edge_index, n_W1, n_b1, E);
        k_finalize<<<1, 256>>>(n_gamma, n_beta, 1.0f / (float)E);
        k_pass2t<<<592, 256>>>(edge_attr, node_features, edge_index,
                               n_W1, n_b1, out, E);
    }
}